// round 1
// baseline (speedup 1.0000x reference)
#include <cuda_runtime.h>
#include <cuda_bf16.h>
#include <cstdint>

#define NN 100000
#define F1 64
#define F2 16

// Scratch (allocation-free rule: __device__ globals)
__device__ float g_deg[NN];
__device__ float g_acc1[NN * F1];
__device__ float g_h1[NN * F1];
__device__ float g_z2[NN * F2];
__device__ float g_acc2[NN * F2];

// ---------------- zero scratch ----------------
__global__ void k_zero() {
    int i = blockIdx.x * blockDim.x + threadIdx.x;
    if (i < NN * F1) g_acc1[i] = 0.f;
    if (i < NN * F2) g_acc2[i] = 0.f;
    if (i < NN)      g_deg[i]  = 0.f;
}

// ---------------- degree count ----------------
__global__ void k_deg(const int* __restrict__ dst, int E) {
    int e = blockIdx.x * blockDim.x + threadIdx.x;
    if (e < E) atomicAdd(&g_deg[dst[e]], 1.0f);
}

// ---------------- layer-1 scatter: acc1[dst] += x[src], width 64 ----------------
__global__ void k_scatter64(const float* __restrict__ x,
                            const int* __restrict__ src,
                            const int* __restrict__ dst, int E) {
    int t = blockIdx.x * blockDim.x + threadIdx.x;
    int e = t >> 4;
    int c = (t & 15) << 2;  // feature chunk (4 floats)
    if (e >= E) return;
    int s = src[e], d = dst[e];
    float4 v = *reinterpret_cast<const float4*>(x + (size_t)s * F1 + c);
    float* p = g_acc1 + (size_t)d * F1 + c;
    asm volatile("red.global.add.v4.f32 [%0], {%1,%2,%3,%4};"
                 :: "l"(p), "f"(v.x), "f"(v.y), "f"(v.z), "f"(v.w) : "memory");
}

// ---------------- layer-1 combine: h1 = relu(x@Ws + (acc1/deg)@Wn + b) ----------------
// 64 nodes/block, 256 threads: thread = (j4 group of 4 feats) x (node lane)
__global__ void __launch_bounds__(256) k_combine1(
    const float* __restrict__ x,
    const float* __restrict__ Ws, const float* __restrict__ Wn,
    const float* __restrict__ b) {
    extern __shared__ float smem[];
    float* sWs   = smem;                 // 64*64
    float* sWn   = smem + 4096;          // 64*64
    float* sX    = smem + 8192;          // 64*64
    float* sA    = smem + 12288;         // 64*64
    float* sDinv = smem + 16384;         // 64
    float* sB    = smem + 16448;         // 64

    int tid   = threadIdx.x;
    int node0 = blockIdx.x * 64;

    for (int i = tid; i < (64 * 64) / 4; i += 256) {
        reinterpret_cast<float4*>(sWs)[i] = reinterpret_cast<const float4*>(Ws)[i];
        reinterpret_cast<float4*>(sWn)[i] = reinterpret_cast<const float4*>(Wn)[i];
    }
    if (tid < 64) {
        sB[tid] = b[tid];
        int n = node0 + tid;
        float d = (n < NN) ? g_deg[n] : 1.f;
        sDinv[tid] = 1.0f / fmaxf(d, 1.0f);
    }
    for (int i = tid; i < 64 * 16; i += 256) {
        int row = i >> 4, c = i & 15;
        int n = node0 + row;
        float4 vx = make_float4(0.f, 0.f, 0.f, 0.f), va = vx;
        if (n < NN) {
            vx = reinterpret_cast<const float4*>(x + (size_t)n * F1)[c];
            va = reinterpret_cast<const float4*>(g_acc1 + (size_t)n * F1)[c];
        }
        reinterpret_cast<float4*>(sX + row * 64)[c] = vx;
        reinterpret_cast<float4*>(sA + row * 64)[c] = va;
    }
    __syncthreads();

    int j4 = (tid & 15) << 2;
    int nb = tid >> 4;  // 0..15
    for (int nn = 0; nn < 4; ++nn) {
        int n = nb + nn * 16;
        float4 as = make_float4(0.f, 0.f, 0.f, 0.f);
        float4 an = make_float4(0.f, 0.f, 0.f, 0.f);
#pragma unroll
        for (int k = 0; k < 64; ++k) {
            float xv = sX[n * 64 + k];
            float av = sA[n * 64 + k];
            float4 ws = *reinterpret_cast<const float4*>(sWs + k * 64 + j4);
            float4 wn = *reinterpret_cast<const float4*>(sWn + k * 64 + j4);
            as.x = fmaf(xv, ws.x, as.x); as.y = fmaf(xv, ws.y, as.y);
            as.z = fmaf(xv, ws.z, as.z); as.w = fmaf(xv, ws.w, as.w);
            an.x = fmaf(av, wn.x, an.x); an.y = fmaf(av, wn.y, an.y);
            an.z = fmaf(av, wn.z, an.z); an.w = fmaf(av, wn.w, an.w);
        }
        int gn = node0 + n;
        if (gn < NN) {
            float dinv = sDinv[n];
            float4 o;
            o.x = fmaxf(fmaf(an.x, dinv, as.x) + sB[j4 + 0], 0.f);
            o.y = fmaxf(fmaf(an.y, dinv, as.y) + sB[j4 + 1], 0.f);
            o.z = fmaxf(fmaf(an.z, dinv, as.z) + sB[j4 + 2], 0.f);
            o.w = fmaxf(fmaf(an.w, dinv, as.w) + sB[j4 + 3], 0.f);
            *reinterpret_cast<float4*>(g_h1 + (size_t)gn * F1 + j4) = o;
        }
    }
}

// ---------------- layer-2 combine: out_self = h1@W2s + b2 ; z2 = h1@W2n ----------------
// 64 nodes/block, 256 threads: thread = (j4 group of 4) x node
__global__ void __launch_bounds__(256) k_combine2(
    const float* __restrict__ Ws, const float* __restrict__ Wn,
    const float* __restrict__ b, float* __restrict__ out) {
    __shared__ float sWs[64 * 16];
    __shared__ float sWn[64 * 16];
    __shared__ float sH[64 * 64];
    __shared__ float sB[16];

    int tid   = threadIdx.x;
    int node0 = blockIdx.x * 64;

    for (int i = tid; i < (64 * 16) / 4; i += 256) {
        reinterpret_cast<float4*>(sWs)[i] = reinterpret_cast<const float4*>(Ws)[i];
        reinterpret_cast<float4*>(sWn)[i] = reinterpret_cast<const float4*>(Wn)[i];
    }
    if (tid < 16) sB[tid] = b[tid];
    for (int i = tid; i < 64 * 16; i += 256) {
        int row = i >> 4, c = i & 15;
        int n = node0 + row;
        float4 v = make_float4(0.f, 0.f, 0.f, 0.f);
        if (n < NN) v = reinterpret_cast<const float4*>(g_h1 + (size_t)n * F1)[c];
        reinterpret_cast<float4*>(sH + row * 64)[c] = v;
    }
    __syncthreads();

    int j4 = (tid & 3) << 2;
    int n  = tid >> 2;  // 0..63
    float4 as = make_float4(0.f, 0.f, 0.f, 0.f);
    float4 an = make_float4(0.f, 0.f, 0.f, 0.f);
#pragma unroll
    for (int k = 0; k < 64; ++k) {
        float hv = sH[n * 64 + k];
        float4 ws = *reinterpret_cast<const float4*>(sWs + k * 16 + j4);
        float4 wn = *reinterpret_cast<const float4*>(sWn + k * 16 + j4);
        as.x = fmaf(hv, ws.x, as.x); as.y = fmaf(hv, ws.y, as.y);
        as.z = fmaf(hv, ws.z, as.z); as.w = fmaf(hv, ws.w, as.w);
        an.x = fmaf(hv, wn.x, an.x); an.y = fmaf(hv, wn.y, an.y);
        an.z = fmaf(hv, wn.z, an.z); an.w = fmaf(hv, wn.w, an.w);
    }
    int gn = node0 + n;
    if (gn < NN) {
        float4 o;
        o.x = as.x + sB[j4 + 0]; o.y = as.y + sB[j4 + 1];
        o.z = as.z + sB[j4 + 2]; o.w = as.w + sB[j4 + 3];
        *reinterpret_cast<float4*>(out + (size_t)gn * F2 + j4) = o;
        *reinterpret_cast<float4*>(g_z2 + (size_t)gn * F2 + j4) = an;
    }
}

// ---------------- layer-2 scatter: acc2[dst] += z2[src], width 16 ----------------
__global__ void k_scatter16(const int* __restrict__ src,
                            const int* __restrict__ dst, int E) {
    int t = blockIdx.x * blockDim.x + threadIdx.x;
    int e = t >> 2;
    int c = (t & 3) << 2;
    if (e >= E) return;
    int s = src[e], d = dst[e];
    float4 v = *reinterpret_cast<const float4*>(g_z2 + (size_t)s * F2 + c);
    float* p = g_acc2 + (size_t)d * F2 + c;
    asm volatile("red.global.add.v4.f32 [%0], {%1,%2,%3,%4};"
                 :: "l"(p), "f"(v.x), "f"(v.y), "f"(v.z), "f"(v.w) : "memory");
}

// ---------------- finalize: out += acc2 / deg ----------------
__global__ void k_final(float* __restrict__ out) {
    int i = blockIdx.x * blockDim.x + threadIdx.x;  // one float4 per thread
    if (i >= NN * F2 / 4) return;
    int n = i >> 2;
    float dinv = 1.0f / fmaxf(g_deg[n], 1.0f);
    float4 o = reinterpret_cast<float4*>(out)[i];
    float4 a = reinterpret_cast<const float4*>(g_acc2)[i];
    o.x = fmaf(a.x, dinv, o.x); o.y = fmaf(a.y, dinv, o.y);
    o.z = fmaf(a.z, dinv, o.z); o.w = fmaf(a.w, dinv, o.w);
    reinterpret_cast<float4*>(out)[i] = o;
}

extern "C" void kernel_launch(void* const* d_in, const int* in_sizes, int n_in,
                              void* d_out, int out_size) {
    const float* x   = (const float*)d_in[0];
    const int*   src = (const int*)d_in[1];
    const int*   dst = (const int*)d_in[2];
    const float* W1s = (const float*)d_in[3];
    const float* W1n = (const float*)d_in[4];
    const float* b1  = (const float*)d_in[5];
    const float* W2s = (const float*)d_in[6];
    const float* W2n = (const float*)d_in[7];
    const float* b2  = (const float*)d_in[8];
    float* out = (float*)d_out;
    int E = in_sizes[1];

    static bool attr_done = false;  // host-side config only; no effect on per-call work
    const int smem1 = (16384 + 128) * sizeof(float);
    if (!attr_done) {
        cudaFuncSetAttribute(k_combine1, cudaFuncAttributeMaxDynamicSharedMemorySize, smem1);
        attr_done = true;
    }

    int nblk;

    nblk = (NN * F1 + 255) / 256;
    k_zero<<<nblk, 256>>>();

    nblk = (E + 255) / 256;
    k_deg<<<nblk, 256>>>(dst, E);

    nblk = (E * 16 + 255) / 256;
    k_scatter64<<<nblk, 256>>>(x, src, dst, E);

    nblk = (NN + 63) / 64;
    k_combine1<<<nblk, 256, smem1>>>(x, W1s, W1n, b1);

    k_combine2<<<nblk, 256>>>(W2s, W2n, b2, out);

    nblk = (E * 4 + 255) / 256;
    k_scatter16<<<nblk, 256>>>(src, dst, E);

    nblk = (NN * F2 / 4 + 255) / 256;
    k_final<<<nblk, 256>>>(out);
}

// round 2
// speedup vs baseline: 3.3182x; 3.3182x over previous
#include <cuda_runtime.h>
#include <cuda_bf16.h>
#include <cstdint>

#define NN 100000
#define F1 64
#define F2 16

// Scratch (allocation-free rule: __device__ globals)
__device__ float g_deg[NN];
__device__ float g_acc1[NN * F1];
__device__ float g_h1[NN * F1];
__device__ float g_z2[NN * F2];
__device__ float g_acc2[NN * F2];

// ---------------- f32x2 packed helpers (sm_100+) ----------------
__device__ __forceinline__ unsigned long long pack2(float v) {
    unsigned long long r;
    asm("mov.b64 %0, {%1, %1};" : "=l"(r) : "f"(v));
    return r;
}
__device__ __forceinline__ unsigned long long fma2(unsigned long long a,
                                                   unsigned long long b,
                                                   unsigned long long c) {
    unsigned long long d;
    asm("fma.rn.f32x2 %0, %1, %2, %3;" : "=l"(d) : "l"(a), "l"(b), "l"(c));
    return d;
}
__device__ __forceinline__ float2 unpack2(unsigned long long v) {
    float2 f;
    asm("mov.b64 {%0, %1}, %2;" : "=f"(f.x), "=f"(f.y) : "l"(v));
    return f;
}

// ---------------- zero scratch ----------------
__global__ void k_zero() {
    int i = blockIdx.x * blockDim.x + threadIdx.x;
    if (i < NN * F1) g_acc1[i] = 0.f;
    if (i < NN * F2) g_acc2[i] = 0.f;
    if (i < NN)      g_deg[i]  = 0.f;
}

// ---------------- degree count ----------------
__global__ void k_deg(const int* __restrict__ dst, int E) {
    int e = blockIdx.x * blockDim.x + threadIdx.x;
    if (e < E) atomicAdd(&g_deg[dst[e]], 1.0f);
}

// ---------------- layer-1 scatter: acc1[dst] += x[src], width 64 ----------------
__global__ void k_scatter64(const float* __restrict__ x,
                            const int* __restrict__ src,
                            const int* __restrict__ dst, int E) {
    int t = blockIdx.x * blockDim.x + threadIdx.x;
    int e = t >> 4;
    int c = (t & 15) << 2;  // feature chunk (4 floats)
    if (e >= E) return;
    int s = src[e], d = dst[e];
    float4 v = *reinterpret_cast<const float4*>(x + (size_t)s * F1 + c);
    float* p = g_acc1 + (size_t)d * F1 + c;
    asm volatile("red.global.add.v4.f32 [%0], {%1,%2,%3,%4};"
                 :: "l"(p), "f"(v.x), "f"(v.y), "f"(v.z), "f"(v.w) : "memory");
}

// ---------------- layer-1 combine: h1 = relu(x@Ws + (acc1/deg)@Wn + b) ----------------
// 64 nodes/block, 256 threads. Thread: jg = tid&15 (4 output cols), ng = tid>>4,
// handles nodes {ng, ng+16, ng+32, ng+48}. k-outer so each weight load is reused
// across 4 nodes. Accumulators are f32x2 pairs (fma.rn.f32x2).
__global__ void __launch_bounds__(256) k_combine1(
    const float* __restrict__ x,
    const float* __restrict__ Ws, const float* __restrict__ Wn,
    const float* __restrict__ b) {
    extern __shared__ float smem[];
    float* sWs   = smem;                 // 64*64
    float* sWn   = smem + 4096;          // 64*64
    float* sX    = smem + 8192;          // 64*64
    float* sA    = smem + 12288;         // 64*64
    float* sDinv = smem + 16384;         // 64
    float* sB    = smem + 16448;         // 64

    int tid   = threadIdx.x;
    int node0 = blockIdx.x * 64;

    for (int i = tid; i < (64 * 64) / 4; i += 256) {
        reinterpret_cast<float4*>(sWs)[i] = reinterpret_cast<const float4*>(Ws)[i];
        reinterpret_cast<float4*>(sWn)[i] = reinterpret_cast<const float4*>(Wn)[i];
    }
    if (tid < 64) {
        sB[tid] = b[tid];
        int n = node0 + tid;
        float d = (n < NN) ? g_deg[n] : 1.f;
        sDinv[tid] = 1.0f / fmaxf(d, 1.0f);
    }
    for (int i = tid; i < 64 * 16; i += 256) {
        int row = i >> 4, c = i & 15;
        int n = node0 + row;
        float4 vx = make_float4(0.f, 0.f, 0.f, 0.f), va = vx;
        if (n < NN) {
            vx = reinterpret_cast<const float4*>(x + (size_t)n * F1)[c];
            va = reinterpret_cast<const float4*>(g_acc1 + (size_t)n * F1)[c];
        }
        reinterpret_cast<float4*>(sX + row * 64)[c] = vx;
        reinterpret_cast<float4*>(sA + row * 64)[c] = va;
    }
    __syncthreads();

    int j4 = (tid & 15) << 2;
    int ng = tid >> 4;  // 0..15

    unsigned long long as0[4], as1[4], an0[4], an1[4];
#pragma unroll
    for (int nn = 0; nn < 4; ++nn) { as0[nn] = 0ull; as1[nn] = 0ull; an0[nn] = 0ull; an1[nn] = 0ull; }

#pragma unroll 1
    for (int k0 = 0; k0 < 64; k0 += 4) {
        float4 xv[4], av[4];
#pragma unroll
        for (int nn = 0; nn < 4; ++nn) {
            int row = (ng + nn * 16) * 64;
            xv[nn] = *reinterpret_cast<const float4*>(sX + row + k0);
            av[nn] = *reinterpret_cast<const float4*>(sA + row + k0);
        }
#pragma unroll
        for (int kk = 0; kk < 4; ++kk) {
            int k = k0 + kk;
            ulonglong2 ws = *reinterpret_cast<const ulonglong2*>(sWs + k * 64 + j4);
            ulonglong2 wn = *reinterpret_cast<const ulonglong2*>(sWn + k * 64 + j4);
#pragma unroll
            for (int nn = 0; nn < 4; ++nn) {
                float xs = (kk == 0) ? xv[nn].x : (kk == 1) ? xv[nn].y : (kk == 2) ? xv[nn].z : xv[nn].w;
                float ax = (kk == 0) ? av[nn].x : (kk == 1) ? av[nn].y : (kk == 2) ? av[nn].z : av[nn].w;
                unsigned long long xx = pack2(xs);
                unsigned long long aa = pack2(ax);
                as0[nn] = fma2(xx, ws.x, as0[nn]);
                as1[nn] = fma2(xx, ws.y, as1[nn]);
                an0[nn] = fma2(aa, wn.x, an0[nn]);
                an1[nn] = fma2(aa, wn.y, an1[nn]);
            }
        }
    }

    float b0 = sB[j4 + 0], b1v = sB[j4 + 1], b2v = sB[j4 + 2], b3v = sB[j4 + 3];
#pragma unroll
    for (int nn = 0; nn < 4; ++nn) {
        int n  = ng + nn * 16;
        int gn = node0 + n;
        if (gn < NN) {
            unsigned long long dd = pack2(sDinv[n]);
            float2 r0 = unpack2(fma2(an0[nn], dd, as0[nn]));
            float2 r1 = unpack2(fma2(an1[nn], dd, as1[nn]));
            float4 o;
            o.x = fmaxf(r0.x + b0,  0.f);
            o.y = fmaxf(r0.y + b1v, 0.f);
            o.z = fmaxf(r1.x + b2v, 0.f);
            o.w = fmaxf(r1.y + b3v, 0.f);
            *reinterpret_cast<float4*>(g_h1 + (size_t)gn * F1 + j4) = o;
        }
    }
}

// ---------------- layer-2 combine: out_self = h1@W2s + b2 ; z2 = h1@W2n ----------------
__global__ void __launch_bounds__(256) k_combine2(
    const float* __restrict__ Ws, const float* __restrict__ Wn,
    const float* __restrict__ b, float* __restrict__ out) {
    __shared__ float sWs[64 * 16];
    __shared__ float sWn[64 * 16];
    __shared__ float sH[64 * 64];
    __shared__ float sB[16];

    int tid   = threadIdx.x;
    int node0 = blockIdx.x * 64;

    for (int i = tid; i < (64 * 16) / 4; i += 256) {
        reinterpret_cast<float4*>(sWs)[i] = reinterpret_cast<const float4*>(Ws)[i];
        reinterpret_cast<float4*>(sWn)[i] = reinterpret_cast<const float4*>(Wn)[i];
    }
    if (tid < 16) sB[tid] = b[tid];
    for (int i = tid; i < 64 * 16; i += 256) {
        int row = i >> 4, c = i & 15;
        int n = node0 + row;
        float4 v = make_float4(0.f, 0.f, 0.f, 0.f);
        if (n < NN) v = reinterpret_cast<const float4*>(g_h1 + (size_t)n * F1)[c];
        reinterpret_cast<float4*>(sH + row * 64)[c] = v;
    }
    __syncthreads();

    int j4 = (tid & 3) << 2;
    int n  = tid >> 2;  // 0..63
    float4 as = make_float4(0.f, 0.f, 0.f, 0.f);
    float4 an = make_float4(0.f, 0.f, 0.f, 0.f);
#pragma unroll 8
    for (int k = 0; k < 64; ++k) {
        float hv = sH[n * 64 + k];
        float4 ws = *reinterpret_cast<const float4*>(sWs + k * 16 + j4);
        float4 wn = *reinterpret_cast<const float4*>(sWn + k * 16 + j4);
        as.x = fmaf(hv, ws.x, as.x); as.y = fmaf(hv, ws.y, as.y);
        as.z = fmaf(hv, ws.z, as.z); as.w = fmaf(hv, ws.w, as.w);
        an.x = fmaf(hv, wn.x, an.x); an.y = fmaf(hv, wn.y, an.y);
        an.z = fmaf(hv, wn.z, an.z); an.w = fmaf(hv, wn.w, an.w);
    }
    int gn = node0 + n;
    if (gn < NN) {
        float4 o;
        o.x = as.x + sB[j4 + 0]; o.y = as.y + sB[j4 + 1];
        o.z = as.z + sB[j4 + 2]; o.w = as.w + sB[j4 + 3];
        *reinterpret_cast<float4*>(out + (size_t)gn * F2 + j4) = o;
        *reinterpret_cast<float4*>(g_z2 + (size_t)gn * F2 + j4) = an;
    }
}

// ---------------- layer-2 scatter: acc2[dst] += z2[src], width 16 ----------------
__global__ void k_scatter16(const int* __restrict__ src,
                            const int* __restrict__ dst, int E) {
    int t = blockIdx.x * blockDim.x + threadIdx.x;
    int e = t >> 2;
    int c = (t & 3) << 2;
    if (e >= E) return;
    int s = src[e], d = dst[e];
    float4 v = *reinterpret_cast<const float4*>(g_z2 + (size_t)s * F2 + c);
    float* p = g_acc2 + (size_t)d * F2 + c;
    asm volatile("red.global.add.v4.f32 [%0], {%1,%2,%3,%4};"
                 :: "l"(p), "f"(v.x), "f"(v.y), "f"(v.z), "f"(v.w) : "memory");
}

// ---------------- finalize: out += acc2 / deg ----------------
__global__ void k_final(float* __restrict__ out) {
    int i = blockIdx.x * blockDim.x + threadIdx.x;  // one float4 per thread
    if (i >= NN * F2 / 4) return;
    int n = i >> 2;
    float dinv = 1.0f / fmaxf(g_deg[n], 1.0f);
    float4 o = reinterpret_cast<float4*>(out)[i];
    float4 a = reinterpret_cast<const float4*>(g_acc2)[i];
    o.x = fmaf(a.x, dinv, o.x); o.y = fmaf(a.y, dinv, o.y);
    o.z = fmaf(a.z, dinv, o.z); o.w = fmaf(a.w, dinv, o.w);
    reinterpret_cast<float4*>(out)[i] = o;
}

extern "C" void kernel_launch(void* const* d_in, const int* in_sizes, int n_in,
                              void* d_out, int out_size) {
    const float* x   = (const float*)d_in[0];
    const int*   src = (const int*)d_in[1];
    const int*   dst = (const int*)d_in[2];
    const float* W1s = (const float*)d_in[3];
    const float* W1n = (const float*)d_in[4];
    const float* b1  = (const float*)d_in[5];
    const float* W2s = (const float*)d_in[6];
    const float* W2n = (const float*)d_in[7];
    const float* b2  = (const float*)d_in[8];
    float* out = (float*)d_out;
    int E = in_sizes[1];

    static bool attr_done = false;  // host-side config only; no effect on per-call work
    const int smem1 = (16384 + 128) * sizeof(float);
    if (!attr_done) {
        cudaFuncSetAttribute(k_combine1, cudaFuncAttributeMaxDynamicSharedMemorySize, smem1);
        attr_done = true;
    }

    int nblk;

    nblk = (NN * F1 + 255) / 256;
    k_zero<<<nblk, 256>>>();

    nblk = (E + 255) / 256;
    k_deg<<<nblk, 256>>>(dst, E);

    nblk = (E * 16 + 255) / 256;
    k_scatter64<<<nblk, 256>>>(x, src, dst, E);

    nblk = (NN + 63) / 64;
    k_combine1<<<nblk, 256, smem1>>>(x, W1s, W1n, b1);

    k_combine2<<<nblk, 256>>>(W2s, W2n, b2, out);

    nblk = (E * 4 + 255) / 256;
    k_scatter16<<<nblk, 256>>>(src, dst, E);

    nblk = (NN * F2 / 4 + 255) / 256;
    k_final<<<nblk, 256>>>(out);
}